// round 17
// baseline (speedup 1.0000x reference)
#include <cuda_runtime.h>
#include <cuda_bf16.h>
#include <cuda_fp16.h>
#include <cstdint>

// LinkPredictorGAT: N_NODES=100000, D=256, E=1000000, H=128
// out_e = relu(z[src]@W1[:256] + z[dst]@W1[256:] + b1) @ W2 + b2
//
// Stage 1 (only compute kernel before edge): fp16 HMMA GEMM, CTA tile 128x128,
//   2 CTAs/SM. W conversion fused: B chunk read from W1 fp32 in natural [k][n]
//   layout, converted to fp16 in registers, stored swizzled; fragments via
//   ldmatrix.x4.trans (identical distribution to the old [n][k]+ldmatrix path).
//   A: LDG Z fp32 -> cvt fp16 in regs -> STS. Both A and B register-double-buffered.
//   UV[M,256](fp16) = Z16@W16 (+b1 on cols<128). PDL trigger after UV stores.
// Stage 2: 8 edges/warp, __ldcg UV gathers; preamble before gridDepSync.

#define MAX_NODES 100000
#define DD 256
#define HH 128

__device__ __half g_UV[(size_t)MAX_NODES * 2 * HH];     // 51.2 MB

__device__ __forceinline__ uint32_t smem_u32(const void* p) {
    uint32_t a;
    asm("{ .reg .u64 t; cvta.to.shared.u64 t, %1; cvt.u32.u64 %0, t; }" : "=r"(a) : "l"(p));
    return a;
}

#define LDMATRIX_X4(r0, r1, r2, r3, addr) \
    asm volatile("ldmatrix.sync.aligned.m8n8.x4.shared.b16 {%0,%1,%2,%3}, [%4];" \
                 : "=r"(r0), "=r"(r1), "=r"(r2), "=r"(r3) : "r"(addr))

#define LDMATRIX_X4_TRANS(r0, r1, r2, r3, addr) \
    asm volatile("ldmatrix.sync.aligned.m8n8.x4.trans.shared.b16 {%0,%1,%2,%3}, [%4];" \
                 : "=r"(r0), "=r"(r1), "=r"(r2), "=r"(r3) : "r"(addr))

#define MMA_F16(d, a0, a1, a2, a3, b0, b1) \
    asm volatile("mma.sync.aligned.m16n8k16.row.col.f32.f16.f16.f32 " \
                 "{%0,%1,%2,%3}, {%4,%5,%6,%7}, {%8,%9}, {%0,%1,%2,%3};" \
                 : "+f"((d)[0]), "+f"((d)[1]), "+f"((d)[2]), "+f"((d)[3]) \
                 : "r"(a0), "r"(a1), "r"(a2), "r"(a3), "r"(b0), "r"(b1))

__device__ __forceinline__ uint32_t h2pack(float a, float b) {
    __half2 h = __floats2half2_rn(a, b);
    return *reinterpret_cast<uint32_t*>(&h);
}

// ---------------- Stage 1: fp16 HMMA GEMM, 128x128 tile, fused W cvt ----------------
// SMEM (64 KB), stages s in {0,1}:
//   A(s): [128 m][64 k] fp16, 128B rows, swizzled    @ s*16384       (16 KB)
//   B(s): [64 k][128 n] fp16, 256B rows, swizzled    @ 32768+s*16384 (16 KB)
#define A_OFF(s)  ((s) * 16384)
#define B_OFF(s)  (32768 + (s) * 16384)
#define GSM_TOTAL 65536

__global__ __launch_bounds__(256, 2)
void uv_gemm_fused_kernel(const float* __restrict__ Z,
                          const float* __restrict__ W1,
                          const float* __restrict__ b1,
                          __half* __restrict__ UV,
                          int M) {
    extern __shared__ char smem[];
    const uint32_t sbase = smem_u32(smem);
    const int tid  = threadIdx.x;
    const int wid  = tid >> 5;
    const int lane = tid & 31;
    const int wm   = wid & 3;          // 4 warp-row groups: 32 rows each
    const int wn   = wid >> 2;         // 2 warp-col groups: 64 cols each
    const int row0 = blockIdx.x * 128;
    const int sl   = blockIdx.y;       // 0: u (W1 rows 0..255), 1: v (rows 256..511)

    const int g  = lane >> 3;
    const int lr = lane & 7;
    const int uAbit = g >> 1;
    const int rA0 = wm * 32 + (g & 1) * 8 + lr;

    float acc[2][8][4];
#pragma unroll
    for (int mi = 0; mi < 2; mi++)
#pragma unroll
        for (int ni = 0; ni < 8; ni++)
#pragma unroll
            for (int q = 0; q < 4; q++) acc[mi][ni][q] = 0.f;

    // ---- A path: idx = tid + i*256 -> r = idx>>4 (0..127 m), q = idx&15 (float4 in k) ----
    auto ldg_A = [&](int c, uint2 (&rA)[8]) {
        const int kc = c * 64;
#pragma unroll
        for (int i = 0; i < 8; ++i) {
            int idx = tid + i * 256;
            int r = idx >> 4;
            int q = idx & 15;
            int gr = row0 + r; if (gr > M - 1) gr = M - 1;
            float4 f = __ldg(reinterpret_cast<const float4*>(Z + (size_t)gr * 256 + kc + q * 4));
            rA[i] = make_uint2(h2pack(f.x, f.y), h2pack(f.z, f.w));
        }
    };
    auto sts_A = [&](int s, const uint2 (&rA)[8]) {
#pragma unroll
        for (int i = 0; i < 8; ++i) {
            int idx = tid + i * 256;
            int r = idx >> 4;
            int q = idx & 15;
            uint32_t soff = (uint32_t)(r * 128 + (((q >> 1) ^ (r & 7)) << 4) + (q & 1) * 8);
            *reinterpret_cast<uint2*>(smem + A_OFF(s) + soff) = rA[i];
        }
    };
    // ---- B path: idx -> r = idx>>5 (0..63 k-row), q = idx&31 (float4 in n) ----
    auto ldg_B = [&](int c, uint2 (&rB)[8]) {
        const int kc = c * 64;
        const float* Wbase = W1 + (size_t)(sl * 256 + kc) * HH;
#pragma unroll
        for (int i = 0; i < 8; ++i) {
            int idx = tid + i * 256;
            int r = idx >> 5;
            int q = idx & 31;
            float4 f = __ldg(reinterpret_cast<const float4*>(Wbase + (size_t)r * HH + q * 4));
            rB[i] = make_uint2(h2pack(f.x, f.y), h2pack(f.z, f.w));
        }
    };
    auto sts_B = [&](int s, const uint2 (&rB)[8]) {
#pragma unroll
        for (int i = 0; i < 8; ++i) {
            int idx = tid + i * 256;
            int r = idx >> 5;
            int q = idx & 31;
            uint32_t soff = (uint32_t)(r * 256 + (((q >> 1) ^ (r & 7)) << 4) + (q & 1) * 8);
            *reinterpret_cast<uint2*>(smem + B_OFF(s) + soff) = rB[i];
        }
    };

    // ---- prologue ----
    uint2 rA[8], rB[8];
    ldg_A(0, rA);
    ldg_B(0, rB);
    sts_A(0, rA);
    sts_B(0, rB);
    ldg_A(1, rA);
    ldg_B(1, rB);

    for (int c = 0; c < 4; ++c) {
        __syncthreads();   // stage c stores visible; prior readers of stage c done

        const int s = c & 1;
        const uint32_t aBase = sbase + A_OFF(s);
        const uint32_t bBase = sbase + B_OFF(s);

#pragma unroll
        for (int kk = 0; kk < 4; ++kk) {
            uint32_t af[2][4];
#pragma unroll
            for (int mi = 0; mi < 2; ++mi) {
                int r = rA0 + mi * 16;
                uint32_t aoff = (uint32_t)(r * 128 + (((kk * 2 + uAbit) ^ lr) << 4));
                LDMATRIX_X4(af[mi][0], af[mi][1], af[mi][2], af[mi][3], aBase + aoff);
            }
#pragma unroll
            for (int np = 0; np < 4; ++np) {
                // B tile is [k][n]; .trans delivers the col-major fragments.
                int kr = kk * 16 + (g & 1) * 8 + lr;            // k-row 0..63
                int nl = wn * 64 + np * 16 + (g >> 1) * 8;      // n col base
                uint32_t boff = (uint32_t)(kr * 256 + ((((nl >> 3) ^ (kr & 7))) << 4));
                uint32_t b0, b1r, b2, b3;
                LDMATRIX_X4_TRANS(b0, b1r, b2, b3, bBase + boff);
#pragma unroll
                for (int mi = 0; mi < 2; ++mi) {
                    MMA_F16(acc[mi][np * 2],     af[mi][0], af[mi][1], af[mi][2], af[mi][3], b0, b1r);
                    MMA_F16(acc[mi][np * 2 + 1], af[mi][0], af[mi][1], af[mi][2], af[mi][3], b2, b3);
                }
            }
        }

        if (c < 3) {
            sts_A((c + 1) & 1, rA);
            sts_B((c + 1) & 1, rB);
            if (c < 2) { ldg_A(c + 2, rA); ldg_B(c + 2, rB); }
        }
    }

    // ---- epilogue: +b1 on cols<128, store fp16 ----
    const int trow  = lane >> 2;
    const int tcol2 = (lane & 3) * 2;
    const int col0  = sl * 128;
#pragma unroll
    for (int mi = 0; mi < 2; ++mi) {
#pragma unroll
        for (int ni = 0; ni < 8; ++ni) {
            int col = col0 + wn * 64 + ni * 8 + tcol2;
            float bx = 0.f, by = 0.f;
            if (col < HH) { bx = __ldg(&b1[col]); by = __ldg(&b1[col + 1]); }
#pragma unroll
            for (int h = 0; h < 2; ++h) {
                int r = row0 + wm * 32 + mi * 16 + trow + h * 8;
                if (r < M) {
                    __half2 v = __floats2half2_rn(acc[mi][ni][h * 2] + bx,
                                                  acc[mi][ni][h * 2 + 1] + by);
                    *reinterpret_cast<__half2*>(UV + (size_t)r * 256 + col) = v;
                }
            }
        }
    }

#if __CUDA_ARCH__ >= 900
    cudaTriggerProgrammaticLaunchCompletion();   // AFTER UV stores: race-free
#endif
}

// ---------------- Stage 2: 8 edges per warp, fp16 UV, L2-only gathers ----------------
__global__ __launch_bounds__(256)
void edge_kernel(const int* __restrict__ eli,
                 const __half* __restrict__ UV,
                 const float* __restrict__ W2,
                 const float* __restrict__ b2,
                 float* __restrict__ out,
                 int E) {
    int gwarp = (blockIdx.x * blockDim.x + threadIdx.x) >> 5;
    int lane  = threadIdx.x & 31;
    int e0 = gwarp * 8;
    if (e0 >= E) return;

    // preamble: independent of GEMM's UV
    float4 w = __ldg(reinterpret_cast<const float4*>(W2) + lane);
    float bb = __ldg(b2);

    int s[8], d[8];
#pragma unroll
    for (int i = 0; i < 8; ++i) {
        int e = min(e0 + i, E - 1);
        s[i] = __ldg(&eli[e]);
        d[i] = __ldg(&eli[(size_t)E + e]);
    }

#if __CUDA_ARCH__ >= 900
    cudaGridDependencySynchronize();   // UV guaranteed written beyond this point
#endif

    uint2 ur[8], vr[8];
#pragma unroll
    for (int i = 0; i < 8; ++i) {
        ur[i] = __ldcg(reinterpret_cast<const uint2*>(UV + (size_t)s[i] * 256) + lane);
        vr[i] = __ldcg(reinterpret_cast<const uint2*>(UV + (size_t)d[i] * 256 + HH) + lane);
    }
    float p[8];
#pragma unroll
    for (int i = 0; i < 8; ++i) {
        const __half2* uh = reinterpret_cast<const __half2*>(&ur[i]);
        const __half2* vh = reinterpret_cast<const __half2*>(&vr[i]);
        float2 u01 = __half22float2(uh[0]);
        float2 u23 = __half22float2(uh[1]);
        float2 v01 = __half22float2(vh[0]);
        float2 v23 = __half22float2(vh[1]);
        p[i] = fmaxf(u01.x + v01.x, 0.f) * w.x + fmaxf(u01.y + v01.y, 0.f) * w.y
             + fmaxf(u23.x + v23.x, 0.f) * w.z + fmaxf(u23.y + v23.y, 0.f) * w.w;
    }
#pragma unroll
    for (int o = 16; o > 0; o >>= 1) {
#pragma unroll
        for (int i = 0; i < 8; ++i)
            p[i] += __shfl_down_sync(0xffffffffu, p[i], o);
    }
    if (lane == 0) {
#pragma unroll
        for (int i = 0; i < 8; ++i)
            if (e0 + i < E) out[e0 + i] = p[i] + bb;
    }
}

extern "C" void kernel_launch(void* const* d_in, const int* in_sizes, int n_in,
                              void* d_out, int out_size) {
    const float* z   = (const float*)d_in[0];
    const int*   eli = (const int*)d_in[1];
    const float* W1  = (const float*)d_in[2];
    const float* b1  = (const float*)d_in[3];
    const float* W2  = (const float*)d_in[4];
    const float* b2  = (const float*)d_in[5];
    float*       out = (float*)d_out;

    const int M = in_sizes[0] / DD;
    const int E = out_size;

    __half* UV;
    cudaGetSymbolAddress((void**)&UV, g_UV);

    cudaFuncSetAttribute(uv_gemm_fused_kernel,
                         cudaFuncAttributeMaxDynamicSharedMemorySize, GSM_TOTAL);

    // kernel 1: GEMM (plain launch; W conversion fused in)
    dim3 ggrid((M + 127) / 128, 2);
    uv_gemm_fused_kernel<<<ggrid, 256, GSM_TOTAL>>>(z, W1, b1, UV, M);

    // kernel 2: edge with PDL serialization against GEMM
    {
        int octs = (E + 7) / 8;
        int warpsPerBlock = 256 / 32;
        int nblk = (octs + warpsPerBlock - 1) / warpsPerBlock;
        cudaLaunchConfig_t cfg = {};
        cfg.gridDim  = dim3(nblk, 1, 1);
        cfg.blockDim = dim3(256, 1, 1);
        cfg.dynamicSmemBytes = 0;
        cudaLaunchAttribute attrs[1];
        attrs[0].id = cudaLaunchAttributeProgrammaticStreamSerialization;
        attrs[0].val.programmaticStreamSerializationAllowed = 1;
        cfg.attrs = attrs;
        cfg.numAttrs = 1;
        cudaLaunchKernelEx(&cfg, edge_kernel, eli, UV, W2, b2, out, E);
    }
}